// round 1
// baseline (speedup 1.0000x reference)
#include <cuda_runtime.h>
#include <math.h>

#define HH 192
#define WW 192
#define HWXY (HH*WW)        // 36864
#define CDIM 48
#define NHEADS 2
#define HD 24
#define KK 7
#define HID 127
#define HID2 254

// ---------------- scratch (static device arrays; no runtime allocation) ----------------
__device__ float g_xn1[CDIM*HWXY];
__device__ float g_q[CDIM*HWXY];     // pixel-major [p][48]
__device__ float g_k[CDIM*HWXY];     // pixel-major
__device__ float g_v[CDIM*HWXY];     // pixel-major
__device__ float g_attn[CDIM*HWXY]; // pixel-major
__device__ float g_xn2[CDIM*HWXY];
__device__ float g_t[HID2*HWXY];
__device__ float g_g[HID*HWXY];
__device__ float g_pmean[CDIM];
__device__ float g_gate[CDIM];

// ---------------- helpers ----------------
__device__ __forceinline__ int win_start(int i, int L) {
    // K=7, D=3
    int st = i - 9;
    if (st < 0) {
        st = i % 3;
    } else if (i + 9 >= L) {
        int imodd = i % 3;
        int a = (L / 3) * 3;
        int b = L - a;
        if (imodd < b) st = L - b + imodd - 18;
        else st = a + imodd - 21;
    }
    return st;
}

// ---------------- K1: LayerNorm1 (per-pixel over 48 channels) ----------------
__global__ void ln1_kernel(const float* __restrict__ x,
                           const float* __restrict__ w,
                           const float* __restrict__ b) {
    int p = blockIdx.x * 256 + threadIdx.x;
    float v[CDIM];
    float s = 0.f;
#pragma unroll
    for (int c = 0; c < CDIM; c++) { v[c] = x[c*HWXY + p]; s += v[c]; }
    float mu = s * (1.f/CDIM);
    float var = 0.f;
#pragma unroll
    for (int c = 0; c < CDIM; c++) { float d = v[c]-mu; var += d*d; }
    float inv = rsqrtf(var*(1.f/CDIM) + 1e-5f);
#pragma unroll
    for (int c = 0; c < CDIM; c++)
        g_xn1[c*HWXY + p] = (v[c]-mu)*inv*w[c] + b[c];
}

// ---------------- K2: QKV projection (tile of 64 pixels per block) ----------------
// dyn smem: weights 144*48, xtile 48*64, out stage 144*65
#define SMEM_QKV ((144*48 + 48*64 + 144*65)*4)
__global__ void qkv_kernel(const float* __restrict__ qw,
                           const float* __restrict__ qb) {
    extern __shared__ float sm[];
    float* sw = sm;                  // [144][48]
    float* sx = sw + 144*48;         // [48][64]
    float* so = sx + 48*64;          // [144][65]
    int p0 = blockIdx.x * 64;
    for (int i = threadIdx.x; i < 144*48; i += 256) sw[i] = qw[i];
    for (int i = threadIdx.x; i < 48*64; i += 256) {
        int c = i >> 6, pix = i & 63;
        sx[i] = g_xn1[c*HWXY + p0 + pix];
    }
    __syncthreads();
    int pix = threadIdx.x & 63;
    int o0  = threadIdx.x >> 6;
    for (int o = o0; o < 144; o += 4) {
        float acc = qb[o];
        const float* wrow = sw + o*48;
#pragma unroll
        for (int c = 0; c < CDIM; c++) acc += wrow[c] * sx[c*64 + pix];
        so[o*65 + pix] = acc;
    }
    __syncthreads();
    const float qs = rsqrtf(24.0f);
    for (int i = threadIdx.x; i < 48*64; i += 256) {
        int p = i / 48, ch = i % 48;
        g_q[(p0+p)*CDIM + ch] = so[ch*65 + p] * qs;
        g_k[(p0+p)*CDIM + ch] = so[(48+ch)*65 + p];
        g_v[(p0+p)*CDIM + ch] = so[(96+ch)*65 + p];
    }
}

// ---------------- K4a: channel means of xn1 ----------------
__global__ void cmean_kernel() {
    __shared__ float red[256];
    int c = blockIdx.x;
    float s = 0.f;
    for (int p = threadIdx.x; p < HWXY; p += 256) s += g_xn1[c*HWXY + p];
    red[threadIdx.x] = s;
    __syncthreads();
    for (int k = 128; k > 0; k >>= 1) {
        if (threadIdx.x < k) red[threadIdx.x] += red[threadIdx.x + k];
        __syncthreads();
    }
    if (threadIdx.x == 0) g_pmean[c] = red[0] * (1.f/HWXY);
}

// ---------------- K4b: ECA gate (conv1d k=7 pad=3 over channels + sigmoid) ----------------
__global__ void gate_kernel(const float* __restrict__ ew) {
    int c = threadIdx.x;
    if (c >= CDIM) return;
    float s = 0.f;
#pragma unroll
    for (int k = 0; k < 7; k++) {
        int cc = c - 3 + k;
        if (cc >= 0 && cc < CDIM) s += ew[k] * g_pmean[cc];
    }
    g_gate[c] = 1.f / (1.f + expf(-s));
}

// ---------------- K3: neighborhood attention (thread = pixel x head) ----------------
__global__ void attn_kernel(const float* __restrict__ rpb) {
    int t = blockIdx.x * 256 + threadIdx.x;
    int p = t >> 1, n = t & 1;
    int i = p / WW, j = p % WW;
    int sti = win_start(i, HH), stj = win_start(j, WW);
    int pbh0 = (sti - i) / 3 + (KK - 1);
    int pbw0 = (stj - j) / 3 + (KK - 1);

    float qreg[HD];
    const float4* qp = reinterpret_cast<const float4*>(g_q + (size_t)p*CDIM + n*HD);
#pragma unroll
    for (int c = 0; c < 6; c++) {
        float4 v4 = qp[c];
        qreg[4*c] = v4.x; qreg[4*c+1] = v4.y; qreg[4*c+2] = v4.z; qreg[4*c+3] = v4.w;
    }

    float logit[KK*KK];
    float m = -1e30f;
    for (int x = 0; x < KK; x++) {
        int ip = sti + x*3;
        const float* brow = rpb + n*169 + (pbh0 + x)*13 + pbw0;
        for (int y = 0; y < KK; y++) {
            int jp = stj + y*3;
            const float4* kp = reinterpret_cast<const float4*>(g_k + (size_t)(ip*WW + jp)*CDIM + n*HD);
            float d = 0.f;
#pragma unroll
            for (int c = 0; c < 6; c++) {
                float4 kk = kp[c];
                d += qreg[4*c]*kk.x + qreg[4*c+1]*kk.y + qreg[4*c+2]*kk.z + qreg[4*c+3]*kk.w;
            }
            d += brow[y];
            logit[x*KK + y] = d;
            m = fmaxf(m, d);
        }
    }
    float s = 0.f;
    for (int e = 0; e < KK*KK; e++) { float w = __expf(logit[e] - m); logit[e] = w; s += w; }
    float inv = 1.f / s;

    float acc[HD];
#pragma unroll
    for (int c = 0; c < HD; c++) acc[c] = 0.f;
    for (int x = 0; x < KK; x++) {
        int ip = sti + x*3;
        for (int y = 0; y < KK; y++) {
            int jp = stj + y*3;
            float w = logit[x*KK + y] * inv;
            const float4* vp = reinterpret_cast<const float4*>(g_v + (size_t)(ip*WW + jp)*CDIM + n*HD);
#pragma unroll
            for (int c = 0; c < 6; c++) {
                float4 vv = vp[c];
                acc[4*c]   += w*vv.x; acc[4*c+1] += w*vv.y;
                acc[4*c+2] += w*vv.z; acc[4*c+3] += w*vv.w;
            }
        }
    }
    float4* op = reinterpret_cast<float4*>(g_attn + (size_t)p*CDIM + n*HD);
#pragma unroll
    for (int c = 0; c < 6; c++)
        op[c] = make_float4(acc[4*c], acc[4*c+1], acc[4*c+2], acc[4*c+3]);
}

// ---------------- K5: proj + gate + residual -> d_out (channel-major) ----------------
__global__ void proj_kernel(const float* __restrict__ x,
                            const float* __restrict__ pw,
                            const float* __restrict__ pb,
                            float* __restrict__ out) {
    __shared__ float sw[48*48];
    __shared__ float sa[48*65];
    int p0 = blockIdx.x * 64;
    for (int i = threadIdx.x; i < 48*48; i += 256) sw[i] = pw[i];
    for (int i = threadIdx.x; i < 48*64; i += 256) {
        int p = i / 48, c = i % 48;
        sa[c*65 + p] = g_attn[(p0+p)*CDIM + c];
    }
    __syncthreads();
    int pix = threadIdx.x & 63;
    int o0  = threadIdx.x >> 6;
    for (int o = o0; o < CDIM; o += 4) {
        float acc = pb[o];
#pragma unroll
        for (int c = 0; c < CDIM; c++) acc += sw[o*48 + c] * sa[c*65 + pix];
        int gi = o*HWXY + p0 + pix;
        out[gi] = x[gi] + g_gate[o] * acc;
    }
}

// ---------------- K6: LayerNorm2 on d_out ----------------
__global__ void ln2_kernel(const float* __restrict__ x,
                           const float* __restrict__ w,
                           const float* __restrict__ b) {
    int p = blockIdx.x * 256 + threadIdx.x;
    float v[CDIM];
    float s = 0.f;
#pragma unroll
    for (int c = 0; c < CDIM; c++) { v[c] = x[c*HWXY + p]; s += v[c]; }
    float mu = s * (1.f/CDIM);
    float var = 0.f;
#pragma unroll
    for (int c = 0; c < CDIM; c++) { float d = v[c]-mu; var += d*d; }
    float inv = rsqrtf(var*(1.f/CDIM) + 1e-5f);
#pragma unroll
    for (int c = 0; c < CDIM; c++)
        g_xn2[c*HWXY + p] = (v[c]-mu)*inv*w[c] + b[c];
}

// ---------------- K7: FFN in-projection (254x48 GEMM per pixel tile of 128) ----------------
#define SMEM_FIN ((HID2*48 + 48*128)*4)
__global__ void ffn_in_kernel(const float* __restrict__ wi) {
    extern __shared__ float sm[];
    float* sw = sm;               // [254][48]
    float* sx = sm + HID2*48;     // [48][128]
    int p0 = blockIdx.x * 128;
    for (int i = threadIdx.x; i < HID2*48; i += 256) sw[i] = wi[i];
    for (int i = threadIdx.x; i < 48*128; i += 256) {
        int c = i >> 7, pix = i & 127;
        sx[i] = g_xn2[c*HWXY + p0 + pix];
    }
    __syncthreads();
    for (int task = threadIdx.x; task < HID2*128; task += 256) {
        int o = task >> 7, pix = task & 127;
        float acc = 0.f;
#pragma unroll
        for (int c = 0; c < CDIM; c++) acc += sw[o*48 + c] * sx[c*128 + pix];
        g_t[(size_t)o*HWXY + p0 + pix] = acc;
    }
}

// ---------------- K8: depthwise 3x3 conv + exact-gelu gating ----------------
__global__ void dwgelu_kernel(const float* __restrict__ wdw) {
    int p = blockIdx.x * 256 + threadIdx.x;
    int o = blockIdx.y;
    int i = p / WW, j = p % WW;
    float a = 0.f, bb = 0.f;
#pragma unroll
    for (int ky = 0; ky < 3; ky++) {
        int ii = i + ky - 1;
        if (ii < 0 || ii >= HH) continue;
#pragma unroll
        for (int kx = 0; kx < 3; kx++) {
            int jj = j + kx - 1;
            if (jj < 0 || jj >= WW) continue;
            int pp = ii*WW + jj;
            a  += wdw[o*9        + ky*3 + kx] * g_t[(size_t)o*HWXY + pp];
            bb += wdw[(o+HID)*9  + ky*3 + kx] * g_t[(size_t)(o+HID)*HWXY + pp];
        }
    }
    float ge = 0.5f * a * (1.f + erff(a * 0.70710678118654752f));
    g_g[(size_t)o*HWXY + p] = ge * bb;
}

// ---------------- K9: FFN out-projection + residual into d_out ----------------
#define SMEM_FOUT ((48*HID + HID*128)*4)
__global__ void ffn_out_kernel(const float* __restrict__ wo,
                               float* __restrict__ out) {
    extern __shared__ float sm[];
    float* sw = sm;             // [48][127]
    float* sg = sm + 48*HID;    // [127][128]
    int p0 = blockIdx.x * 128;
    for (int i = threadIdx.x; i < 48*HID; i += 256) sw[i] = wo[i];
    for (int i = threadIdx.x; i < HID*128; i += 256) {
        int o = i >> 7, pix = i & 127;
        sg[i] = g_g[(size_t)o*HWXY + p0 + pix];
    }
    __syncthreads();
    for (int task = threadIdx.x; task < 48*128; task += 256) {
        int o = task >> 7, pix = task & 127;
        float acc = 0.f;
#pragma unroll
        for (int c = 0; c < HID; c++) acc += sw[o*HID + c] * sg[c*128 + pix];
        out[o*HWXY + p0 + pix] += acc;
    }
}

// ---------------- launch ----------------
extern "C" void kernel_launch(void* const* d_in, const int* in_sizes, int n_in,
                              void* d_out, int out_size) {
    const float* x      = (const float*)d_in[0];
    const float* ln1_w  = (const float*)d_in[1];
    const float* ln1_b  = (const float*)d_in[2];
    const float* qkv_w  = (const float*)d_in[3];
    const float* qkv_b  = (const float*)d_in[4];
    const float* rpb    = (const float*)d_in[5];
    const float* proj_w = (const float*)d_in[6];
    const float* proj_b = (const float*)d_in[7];
    const float* eca_w  = (const float*)d_in[8];
    const float* ln2_w  = (const float*)d_in[9];
    const float* ln2_b  = (const float*)d_in[10];
    const float* w_in   = (const float*)d_in[11];
    const float* w_dw   = (const float*)d_in[12];
    const float* w_out  = (const float*)d_in[13];
    float* out = (float*)d_out;

    cudaFuncSetAttribute(qkv_kernel,     cudaFuncAttributeMaxDynamicSharedMemorySize, SMEM_QKV);
    cudaFuncSetAttribute(ffn_in_kernel,  cudaFuncAttributeMaxDynamicSharedMemorySize, SMEM_FIN);
    cudaFuncSetAttribute(ffn_out_kernel, cudaFuncAttributeMaxDynamicSharedMemorySize, SMEM_FOUT);

    ln1_kernel<<<HWXY/256, 256>>>(x, ln1_w, ln1_b);
    qkv_kernel<<<HWXY/64, 256, SMEM_QKV>>>(qkv_w, qkv_b);
    cmean_kernel<<<CDIM, 256>>>();
    gate_kernel<<<1, 64>>>(eca_w);
    attn_kernel<<<HWXY*NHEADS/256, 256>>>(rpb);
    proj_kernel<<<HWXY/64, 256>>>(x, proj_w, proj_b, out);
    ln2_kernel<<<HWXY/256, 256>>>(out, ln2_w, ln2_b);
    ffn_in_kernel<<<HWXY/128, 256, SMEM_FIN>>>(w_in);
    dwgelu_kernel<<<dim3(HWXY/256, HID), 256>>>(w_dw);
    ffn_out_kernel<<<HWXY/128, 256, SMEM_FOUT>>>(w_out, out);
}

// round 2
// speedup vs baseline: 1.2212x; 1.2212x over previous
#include <cuda_runtime.h>
#include <math.h>

#define HH 192
#define WW 192
#define HWXY (HH*WW)        // 36864
#define CDIM 48
#define NHEADS 2
#define HD 24
#define KK 7
#define HID 127
#define HID2 254

// ---------------- scratch ----------------
__device__ float g_xn1[CDIM*HWXY];
__device__ float g_q[CDIM*HWXY];     // pixel-major [p][48]
__device__ float g_k[CDIM*HWXY];
__device__ float g_v[CDIM*HWXY];
__device__ float g_attn[CDIM*HWXY]; // pixel-major
__device__ float g_xn2[CDIM*HWXY];  // channel-major
__device__ float g_t[HID2*HWXY];    // channel-major
__device__ float g_g[HID*HWXY];     // channel-major
__device__ float g_pmean_part[CDIM*16];

// ---------------- helpers ----------------
__device__ __forceinline__ int win_start(int i, int L) {
    int st = i - 9;
    if (st < 0) {
        st = i % 3;
    } else if (i + 9 >= L) {
        int imodd = i % 3;
        int a = (L / 3) * 3;
        int b = L - a;
        if (imodd < b) st = L - b + imodd - 18;
        else st = a + imodd - 21;
    }
    return st;
}

// ---------------- K1: LayerNorm1 ----------------
__global__ void ln1_kernel(const float* __restrict__ x,
                           const float* __restrict__ w,
                           const float* __restrict__ b) {
    int p = blockIdx.x * 256 + threadIdx.x;
    float v[CDIM];
    float s = 0.f;
#pragma unroll
    for (int c = 0; c < CDIM; c++) { v[c] = x[c*HWXY + p]; s += v[c]; }
    float mu = s * (1.f/CDIM);
    float var = 0.f;
#pragma unroll
    for (int c = 0; c < CDIM; c++) { float d = v[c]-mu; var += d*d; }
    float inv = rsqrtf(var*(1.f/CDIM) + 1e-5f);
#pragma unroll
    for (int c = 0; c < CDIM; c++)
        g_xn1[c*HWXY + p] = (v[c]-mu)*inv*w[c] + b[c];
}

// ---------------- K2: QKV projection, register-tiled 8o x 8px ----------------
// smem: sw[144][48] + sx[48][128] + so[144][132]
#define QKV_SMEM ((144*48 + 48*128 + 144*132)*4)
__global__ void __launch_bounds__(288) qkv_kernel(const float* __restrict__ qw,
                                                  const float* __restrict__ qb) {
    extern __shared__ float sm[];
    float* sw = sm;             // [144][48]
    float* sx = sm + 144*48;    // [48][128]
    float* so = sx + 48*128;    // [144][132]
    int tid = threadIdx.x;
    int p0 = blockIdx.x * 128;

    for (int i = tid; i < 144*48; i += 288) sw[i] = qw[i];
    for (int i = tid; i < 48*128; i += 288) {
        int c = i >> 7, px = i & 127;
        sx[i] = g_xn1[c*HWXY + p0 + px];
    }
    __syncthreads();

    int og = tid / 16, pg = tid & 15;   // og 0..17, pg 0..15
    int o0 = og * 8, px0 = pg * 8;
    float acc[8][8];
#pragma unroll
    for (int a = 0; a < 8; a++)
#pragma unroll
        for (int bi = 0; bi < 8; bi++) acc[a][bi] = 0.f;

    for (int c4 = 0; c4 < 48; c4 += 4) {
        float xs[4][8];
#pragma unroll
        for (int r = 0; r < 4; r++) {
            float4 a = *(const float4*)&sx[(c4+r)*128 + px0];
            float4 b = *(const float4*)&sx[(c4+r)*128 + px0 + 4];
            xs[r][0]=a.x; xs[r][1]=a.y; xs[r][2]=a.z; xs[r][3]=a.w;
            xs[r][4]=b.x; xs[r][5]=b.y; xs[r][6]=b.z; xs[r][7]=b.w;
        }
#pragma unroll
        for (int oo = 0; oo < 8; oo++) {
            float4 w4 = *(const float4*)&sw[(o0+oo)*48 + c4];
            float wv[4] = {w4.x, w4.y, w4.z, w4.w};
#pragma unroll
            for (int r = 0; r < 4; r++)
#pragma unroll
                for (int px = 0; px < 8; px++)
                    acc[oo][px] += wv[r] * xs[r][px];
        }
    }
#pragma unroll
    for (int oo = 0; oo < 8; oo++) {
        float b = qb[o0+oo];
#pragma unroll
        for (int px = 0; px < 8; px++)
            so[(o0+oo)*132 + px0 + px] = acc[oo][px] + b;
    }
    __syncthreads();

    const float qs = rsqrtf(24.0f);
    for (int f = tid; f < 3*128*12; f += 288) {
        int tensor = f / 1536;
        int rem = f % 1536;
        int px = rem / 12;
        int c4 = rem % 12;
        int o = tensor*48 + c4*4;
        float4 v;
        v.x = so[(o+0)*132 + px];
        v.y = so[(o+1)*132 + px];
        v.z = so[(o+2)*132 + px];
        v.w = so[(o+3)*132 + px];
        float* dst = (tensor == 0) ? g_q : (tensor == 1) ? g_k : g_v;
        if (tensor == 0) { v.x*=qs; v.y*=qs; v.z*=qs; v.w*=qs; }
        *(float4*)&dst[(size_t)(p0+px)*CDIM + c4*4] = v;
    }
}

// ---------------- K3: channel mean partials (deterministic) ----------------
__global__ void cmean_kernel() {
    __shared__ float red[256];
    int c = blockIdx.x, chunk = blockIdx.y;
    int base = chunk * 2304;
    float s = 0.f;
    for (int p = threadIdx.x; p < 2304; p += 256) s += g_xn1[c*HWXY + base + p];
    red[threadIdx.x] = s;
    __syncthreads();
    for (int k = 128; k > 0; k >>= 1) {
        if (threadIdx.x < k) red[threadIdx.x] += red[threadIdx.x + k];
        __syncthreads();
    }
    if (threadIdx.x == 0) g_pmean_part[c*16 + chunk] = red[0];
}

// ---------------- K4: neighborhood attention ----------------
__global__ void attn_kernel(const float* __restrict__ rpb) {
    int t = blockIdx.x * 256 + threadIdx.x;
    int p = t >> 1, n = t & 1;
    int i = p / WW, j = p % WW;
    int sti = win_start(i, HH), stj = win_start(j, WW);
    int pbh0 = (sti - i) / 3 + (KK - 1);
    int pbw0 = (stj - j) / 3 + (KK - 1);

    float qreg[HD];
    const float4* qp = reinterpret_cast<const float4*>(g_q + (size_t)p*CDIM + n*HD);
#pragma unroll
    for (int c = 0; c < 6; c++) {
        float4 v4 = qp[c];
        qreg[4*c] = v4.x; qreg[4*c+1] = v4.y; qreg[4*c+2] = v4.z; qreg[4*c+3] = v4.w;
    }

    float logit[KK*KK];
    float m = -1e30f;
    for (int x = 0; x < KK; x++) {
        int ip = sti + x*3;
        const float* brow = rpb + n*169 + (pbh0 + x)*13 + pbw0;
        for (int y = 0; y < KK; y++) {
            int jp = stj + y*3;
            const float4* kp = reinterpret_cast<const float4*>(g_k + (size_t)(ip*WW + jp)*CDIM + n*HD);
            float d = 0.f;
#pragma unroll
            for (int c = 0; c < 6; c++) {
                float4 kk = kp[c];
                d += qreg[4*c]*kk.x + qreg[4*c+1]*kk.y + qreg[4*c+2]*kk.z + qreg[4*c+3]*kk.w;
            }
            d += brow[y];
            logit[x*KK + y] = d;
            m = fmaxf(m, d);
        }
    }
    float s = 0.f;
    for (int e = 0; e < KK*KK; e++) { float w = __expf(logit[e] - m); logit[e] = w; s += w; }
    float inv = 1.f / s;

    float acc[HD];
#pragma unroll
    for (int c = 0; c < HD; c++) acc[c] = 0.f;
    for (int x = 0; x < KK; x++) {
        int ip = sti + x*3;
        for (int y = 0; y < KK; y++) {
            int jp = stj + y*3;
            float w = logit[x*KK + y] * inv;
            const float4* vp = reinterpret_cast<const float4*>(g_v + (size_t)(ip*WW + jp)*CDIM + n*HD);
#pragma unroll
            for (int c = 0; c < 6; c++) {
                float4 vv = vp[c];
                acc[4*c]   += w*vv.x; acc[4*c+1] += w*vv.y;
                acc[4*c+2] += w*vv.z; acc[4*c+3] += w*vv.w;
            }
        }
    }
    float4* op = reinterpret_cast<float4*>(g_attn + (size_t)p*CDIM + n*HD);
#pragma unroll
    for (int c = 0; c < 6; c++)
        op[c] = make_float4(acc[4*c], acc[4*c+1], acc[4*c+2], acc[4*c+3]);
}

// ---------------- K5: proj + ECA gate + residual + LN2 fused ----------------
// smem: sw[48][48] + sa[48][132] + so[48][132] + smean[48] + sgate[48]
#define PROJ_SMEM ((48*48 + 48*132 + 48*132 + 48 + 48)*4)
__global__ void __launch_bounds__(192) proj_kernel(const float* __restrict__ x,
                            const float* __restrict__ pw,
                            const float* __restrict__ pb,
                            const float* __restrict__ ew,
                            const float* __restrict__ ln2w,
                            const float* __restrict__ ln2b,
                            float* __restrict__ out) {
    extern __shared__ float sm[];
    float* sw = sm;                 // [48][48]
    float* sa = sm + 48*48;         // [48][132]
    float* so = sa + 48*132;        // [48][132]
    float* smean = so + 48*132;     // [48]
    float* sgate = smean + 48;      // [48]
    int tid = threadIdx.x;
    int p0 = blockIdx.x * 128;

    for (int i = tid; i < 48*48; i += 192) sw[i] = pw[i];
    for (int i = tid; i < 48*128; i += 192) {
        int px = i / 48, c = i % 48;
        sa[c*132 + px] = g_attn[(size_t)(p0+px)*CDIM + c];
    }
    if (tid < 48) {
        float s = 0.f;
#pragma unroll
        for (int k = 0; k < 16; k++) s += g_pmean_part[tid*16 + k];
        smean[tid] = s * (1.f/HWXY);
    }
    __syncthreads();
    if (tid < 48) {
        float s = 0.f;
#pragma unroll
        for (int k = 0; k < 7; k++) {
            int cc = tid - 3 + k;
            if (cc >= 0 && cc < CDIM) s += ew[k] * smean[cc];
        }
        sgate[tid] = 1.f / (1.f + expf(-s));
    }

    int og = tid >> 4, pg = tid & 15;   // og 0..11, pg 0..15
    int o0 = og * 4, px0 = pg * 8;
    float acc[4][8];
#pragma unroll
    for (int a = 0; a < 4; a++)
#pragma unroll
        for (int bi = 0; bi < 8; bi++) acc[a][bi] = 0.f;

    for (int c4 = 0; c4 < 48; c4 += 4) {
        float xs[4][8];
#pragma unroll
        for (int r = 0; r < 4; r++) {
            float4 a = *(const float4*)&sa[(c4+r)*132 + px0];
            float4 b = *(const float4*)&sa[(c4+r)*132 + px0 + 4];
            xs[r][0]=a.x; xs[r][1]=a.y; xs[r][2]=a.z; xs[r][3]=a.w;
            xs[r][4]=b.x; xs[r][5]=b.y; xs[r][6]=b.z; xs[r][7]=b.w;
        }
#pragma unroll
        for (int oo = 0; oo < 4; oo++) {
            float4 w4 = *(const float4*)&sw[(o0+oo)*48 + c4];
            float wv[4] = {w4.x, w4.y, w4.z, w4.w};
#pragma unroll
            for (int r = 0; r < 4; r++)
#pragma unroll
                for (int px = 0; px < 8; px++)
                    acc[oo][px] += wv[r] * xs[r][px];
        }
    }
    __syncthreads();  // sgate visible

#pragma unroll
    for (int oo = 0; oo < 4; oo++) {
        int o = o0 + oo;
        float g = sgate[o];
        float b = pb[o];
        float4 xv1 = *(const float4*)&x[(size_t)o*HWXY + p0 + px0];
        float4 xv2 = *(const float4*)&x[(size_t)o*HWXY + p0 + px0 + 4];
        float vals[8];
        vals[0] = xv1.x + g*(acc[oo][0]+b); vals[1] = xv1.y + g*(acc[oo][1]+b);
        vals[2] = xv1.z + g*(acc[oo][2]+b); vals[3] = xv1.w + g*(acc[oo][3]+b);
        vals[4] = xv2.x + g*(acc[oo][4]+b); vals[5] = xv2.y + g*(acc[oo][5]+b);
        vals[6] = xv2.z + g*(acc[oo][6]+b); vals[7] = xv2.w + g*(acc[oo][7]+b);
        *(float4*)&out[(size_t)o*HWXY + p0 + px0]     = make_float4(vals[0],vals[1],vals[2],vals[3]);
        *(float4*)&out[(size_t)o*HWXY + p0 + px0 + 4] = make_float4(vals[4],vals[5],vals[6],vals[7]);
#pragma unroll
        for (int px = 0; px < 8; px++) so[o*132 + px0 + px] = vals[px];
    }
    __syncthreads();

    // fused LN2: one thread per pixel
    if (tid < 128) {
        int px = tid;
        float v[CDIM];
        float s = 0.f;
#pragma unroll
        for (int c = 0; c < CDIM; c++) { v[c] = so[c*132 + px]; s += v[c]; }
        float mu = s * (1.f/CDIM);
        float var = 0.f;
#pragma unroll
        for (int c = 0; c < CDIM; c++) { float d = v[c]-mu; var += d*d; }
        float inv = rsqrtf(var*(1.f/CDIM) + 1e-5f);
#pragma unroll
        for (int c = 0; c < CDIM; c++)
            g_xn2[c*HWXY + p0 + px] = (v[c]-mu)*inv*ln2w[c] + ln2b[c];
    }
}

// ---------------- K6: FFN in-projection, 8o x 8px tiles ----------------
// smem: sw[256][48] (pad) + sx[48][128]
#define FIN_SMEM ((256*48 + 48*128)*4)
__global__ void __launch_bounds__(512) ffn_in_kernel(const float* __restrict__ wi) {
    extern __shared__ float sm[];
    float* sw = sm;               // [256][48], rows >=254 zero
    float* sx = sm + 256*48;      // [48][128]
    int tid = threadIdx.x;
    int p0 = blockIdx.x * 128;

    for (int i = tid; i < 256*48; i += 512) sw[i] = (i < HID2*48) ? wi[i] : 0.f;
    for (int i = tid; i < 48*128; i += 512) {
        int c = i >> 7, px = i & 127;
        sx[i] = g_xn2[c*HWXY + p0 + px];
    }
    __syncthreads();

    int og = tid >> 4, pg = tid & 15;   // og 0..31, pg 0..15
    int o0 = og * 8, px0 = pg * 8;
    float acc[8][8];
#pragma unroll
    for (int a = 0; a < 8; a++)
#pragma unroll
        for (int bi = 0; bi < 8; bi++) acc[a][bi] = 0.f;

    for (int c4 = 0; c4 < 48; c4 += 4) {
        float xs[4][8];
#pragma unroll
        for (int r = 0; r < 4; r++) {
            float4 a = *(const float4*)&sx[(c4+r)*128 + px0];
            float4 b = *(const float4*)&sx[(c4+r)*128 + px0 + 4];
            xs[r][0]=a.x; xs[r][1]=a.y; xs[r][2]=a.z; xs[r][3]=a.w;
            xs[r][4]=b.x; xs[r][5]=b.y; xs[r][6]=b.z; xs[r][7]=b.w;
        }
#pragma unroll
        for (int oo = 0; oo < 8; oo++) {
            float4 w4 = *(const float4*)&sw[(o0+oo)*48 + c4];
            float wv[4] = {w4.x, w4.y, w4.z, w4.w};
#pragma unroll
            for (int r = 0; r < 4; r++)
#pragma unroll
                for (int px = 0; px < 8; px++)
                    acc[oo][px] += wv[r] * xs[r][px];
        }
    }
#pragma unroll
    for (int oo = 0; oo < 8; oo++) {
        int o = o0 + oo;
        if (o < HID2) {
            *(float4*)&g_t[(size_t)o*HWXY + p0 + px0]     = make_float4(acc[oo][0],acc[oo][1],acc[oo][2],acc[oo][3]);
            *(float4*)&g_t[(size_t)o*HWXY + p0 + px0 + 4] = make_float4(acc[oo][4],acc[oo][5],acc[oo][6],acc[oo][7]);
        }
    }
}

// ---------------- K7: depthwise 3x3 + exact-gelu gating, smem row-band tiled ----------------
__global__ void dwgelu_kernel(const float* __restrict__ wdw) {
    __shared__ float sA[6*192];
    __shared__ float sB[6*192];
    __shared__ float swc[18];
    int o = blockIdx.y;
    int r0 = blockIdx.x * 4;
    int tid = threadIdx.x;

    if (tid < 9)  swc[tid] = wdw[o*9 + tid];
    else if (tid < 18) swc[tid] = wdw[(o+HID)*9 + tid - 9];

    for (int i = tid; i < 6*192; i += 256) {
        int rr = i / 192, col = i - rr*192;
        int row = r0 - 1 + rr;
        bool ok = (row >= 0) && (row < HH);
        sA[i] = ok ? g_t[(size_t)o*HWXY + row*WW + col] : 0.f;
        sB[i] = ok ? g_t[(size_t)(o+HID)*HWXY + row*WW + col] : 0.f;
    }
    __syncthreads();

    for (int idx = tid; idx < 4*192; idx += 256) {
        int orow = idx / 192, col = idx - orow*192;
        int sbase = (orow + 1) * 192 + col;  // center row in smem (offset by halo)
        float a = 0.f, bb = 0.f;
#pragma unroll
        for (int ky = 0; ky < 3; ky++) {
            int rb = sbase + (ky-1)*192;
#pragma unroll
            for (int kx = 0; kx < 3; kx++) {
                int cc = col + kx - 1;
                if (cc < 0 || cc >= WW) continue;
                a  += swc[ky*3+kx]     * sA[rb + kx - 1];
                bb += swc[9 + ky*3+kx] * sB[rb + kx - 1];
            }
        }
        float ge = 0.5f * a * (1.f + erff(a * 0.70710678118654752f));
        g_g[(size_t)o*HWXY + (r0+orow)*WW + col] = ge * bb;
    }
}

// ---------------- K8: FFN out-projection + residual ----------------
// smem: sw[48][128] (K padded) + sg[128][128] (row 127 zero)
#define FOUT_SMEM ((48*128 + 128*128)*4)
__global__ void __launch_bounds__(192) ffn_out_kernel(const float* __restrict__ wo,
                               float* __restrict__ out) {
    extern __shared__ float sm[];
    float* sw = sm;             // [48][128]
    float* sg = sm + 48*128;    // [128][128]
    int tid = threadIdx.x;
    int p0 = blockIdx.x * 128;

    for (int i = tid; i < 48*128; i += 192) {
        int o = i >> 7, c = i & 127;
        sw[i] = (c < HID) ? wo[o*HID + c] : 0.f;
    }
    for (int i = tid; i < 128*128; i += 192) {
        int c = i >> 7, px = i & 127;
        sg[i] = (c < HID) ? g_g[(size_t)c*HWXY + p0 + px] : 0.f;
    }
    __syncthreads();

    int og = tid >> 4, pg = tid & 15;   // og 0..11, pg 0..15
    int o0 = og * 4, px0 = pg * 8;
    float acc[4][8];
#pragma unroll
    for (int a = 0; a < 4; a++)
#pragma unroll
        for (int bi = 0; bi < 8; bi++) acc[a][bi] = 0.f;

    for (int c4 = 0; c4 < 128; c4 += 4) {
        float xs[4][8];
#pragma unroll
        for (int r = 0; r < 4; r++) {
            float4 a = *(const float4*)&sg[(c4+r)*128 + px0];
            float4 b = *(const float4*)&sg[(c4+r)*128 + px0 + 4];
            xs[r][0]=a.x; xs[r][1]=a.y; xs[r][2]=a.z; xs[r][3]=a.w;
            xs[r][4]=b.x; xs[r][5]=b.y; xs[r][6]=b.z; xs[r][7]=b.w;
        }
#pragma unroll
        for (int oo = 0; oo < 4; oo++) {
            float4 w4 = *(const float4*)&sw[(o0+oo)*128 + c4];
            float wv[4] = {w4.x, w4.y, w4.z, w4.w};
#pragma unroll
            for (int r = 0; r < 4; r++)
#pragma unroll
                for (int px = 0; px < 8; px++)
                    acc[oo][px] += wv[r] * xs[r][px];
        }
    }
#pragma unroll
    for (int oo = 0; oo < 4; oo++) {
        int o = o0 + oo;
        float4* op1 = (float4*)&out[(size_t)o*HWXY + p0 + px0];
        float4* op2 = (float4*)&out[(size_t)o*HWXY + p0 + px0 + 4];
        float4 c1 = *op1, c2 = *op2;
        c1.x += acc[oo][0]; c1.y += acc[oo][1]; c1.z += acc[oo][2]; c1.w += acc[oo][3];
        c2.x += acc[oo][4]; c2.y += acc[oo][5]; c2.z += acc[oo][6]; c2.w += acc[oo][7];
        *op1 = c1; *op2 = c2;
    }
}

// ---------------- launch ----------------
extern "C" void kernel_launch(void* const* d_in, const int* in_sizes, int n_in,
                              void* d_out, int out_size) {
    const float* x      = (const float*)d_in[0];
    const float* ln1_w  = (const float*)d_in[1];
    const float* ln1_b  = (const float*)d_in[2];
    const float* qkv_w  = (const float*)d_in[3];
    const float* qkv_b  = (const float*)d_in[4];
    const float* rpb    = (const float*)d_in[5];
    const float* proj_w = (const float*)d_in[6];
    const float* proj_b = (const float*)d_in[7];
    const float* eca_w  = (const float*)d_in[8];
    const float* ln2_w  = (const float*)d_in[9];
    const float* ln2_b  = (const float*)d_in[10];
    const float* w_in   = (const float*)d_in[11];
    const float* w_dw   = (const float*)d_in[12];
    const float* w_out  = (const float*)d_in[13];
    float* out = (float*)d_out;

    cudaFuncSetAttribute(qkv_kernel,     cudaFuncAttributeMaxDynamicSharedMemorySize, QKV_SMEM);
    cudaFuncSetAttribute(proj_kernel,    cudaFuncAttributeMaxDynamicSharedMemorySize, PROJ_SMEM);
    cudaFuncSetAttribute(ffn_in_kernel,  cudaFuncAttributeMaxDynamicSharedMemorySize, FIN_SMEM);
    cudaFuncSetAttribute(ffn_out_kernel, cudaFuncAttributeMaxDynamicSharedMemorySize, FOUT_SMEM);

    ln1_kernel<<<HWXY/256, 256>>>(x, ln1_w, ln1_b);
    qkv_kernel<<<HWXY/128, 288, QKV_SMEM>>>(qkv_w, qkv_b);
    cmean_kernel<<<dim3(CDIM,16), 256>>>();
    attn_kernel<<<HWXY*NHEADS/256, 256>>>(rpb);
    proj_kernel<<<HWXY/128, 192, PROJ_SMEM>>>(x, proj_w, proj_b, eca_w, ln2_w, ln2_b, out);
    ffn_in_kernel<<<HWXY/128, 512, FIN_SMEM>>>(w_in);
    dwgelu_kernel<<<dim3(HH/4, HID), 256>>>(w_dw);
    ffn_out_kernel<<<HWXY/128, 192, FOUT_SMEM>>>(w_out, out);
}

// round 3
// speedup vs baseline: 1.4062x; 1.1515x over previous
#include <cuda_runtime.h>
#include <math.h>

#define HH 192
#define WW 192
#define HWXY (HH*WW)        // 36864
#define CDIM 48
#define NHEADS 2
#define HD 24
#define KK 7
#define HID 127
#define HID2 254
#define CG 64               // coset grid 64x64
#define NQKVBLK 288         // qkv blocks (36864/128)

// ---------------- scratch ----------------
__device__ float g_qc[NHEADS*9*CG*CG*HD];   // [head][coset][row*64+col][24]
__device__ float g_kc[NHEADS*9*CG*CG*HD];
__device__ float g_vc[NHEADS*9*CG*CG*HD];
__device__ float g_attn[CDIM*HWXY];         // pixel-major [p][48]
__device__ float g_xn2[CDIM*HWXY];          // channel-major
__device__ float g_t[HID2*HWXY];            // channel-major
__device__ float g_g[HID*HWXY];             // channel-major
__device__ float g_pmean_part[NQKVBLK*CDIM];

// ---------------- K1: LN1 + QKV projection fused, writes coset layout ----------------
// smem: sw[144][48] + sx[48][132] + so[144][132]
#define QKV_SMEM ((144*48 + 48*132 + 144*132)*4)
__global__ void __launch_bounds__(288) qkv_kernel(const float* __restrict__ x,
                                                  const float* __restrict__ lnw,
                                                  const float* __restrict__ lnb,
                                                  const float* __restrict__ qw,
                                                  const float* __restrict__ qb) {
    extern __shared__ float sm[];
    float* sw = sm;             // [144][48]
    float* sx = sm + 144*48;    // [48][132]
    float* so = sx + 48*132;    // [144][132]
    int tid = threadIdx.x;
    int p0 = blockIdx.x * 128;

    for (int i = tid; i < 144*48; i += 288) sw[i] = qw[i];
    // inline LayerNorm1: one thread per pixel
    if (tid < 128) {
        int p = p0 + tid;
        float v[CDIM];
        float s = 0.f;
#pragma unroll
        for (int c = 0; c < CDIM; c++) { v[c] = x[c*HWXY + p]; s += v[c]; }
        float mu = s * (1.f/CDIM);
        float var = 0.f;
#pragma unroll
        for (int c = 0; c < CDIM; c++) { float d = v[c]-mu; var += d*d; }
        float inv = rsqrtf(var*(1.f/CDIM) + 1e-5f);
#pragma unroll
        for (int c = 0; c < CDIM; c++)
            sx[c*132 + tid] = (v[c]-mu)*inv*lnw[c] + lnb[c];
    }
    __syncthreads();

    // channel-mean partials for ECA gate
    if (tid < 48) {
        float s = 0.f;
        for (int px = 0; px < 128; px++) s += sx[tid*132 + px];
        g_pmean_part[blockIdx.x*48 + tid] = s;
    }

    int og = tid / 16, pg = tid & 15;   // og 0..17, pg 0..15
    int o0 = og * 8, px0 = pg * 8;
    float acc[8][8];
#pragma unroll
    for (int a = 0; a < 8; a++)
#pragma unroll
        for (int bi = 0; bi < 8; bi++) acc[a][bi] = 0.f;

    for (int c4 = 0; c4 < 48; c4 += 4) {
        float xs[4][8];
#pragma unroll
        for (int r = 0; r < 4; r++) {
            float4 a = *(const float4*)&sx[(c4+r)*132 + px0];
            float4 b = *(const float4*)&sx[(c4+r)*132 + px0 + 4];
            xs[r][0]=a.x; xs[r][1]=a.y; xs[r][2]=a.z; xs[r][3]=a.w;
            xs[r][4]=b.x; xs[r][5]=b.y; xs[r][6]=b.z; xs[r][7]=b.w;
        }
#pragma unroll
        for (int oo = 0; oo < 8; oo++) {
            float4 w4 = *(const float4*)&sw[(o0+oo)*48 + c4];
            float wv[4] = {w4.x, w4.y, w4.z, w4.w};
#pragma unroll
            for (int r = 0; r < 4; r++)
#pragma unroll
                for (int px = 0; px < 8; px++)
                    acc[oo][px] += wv[r] * xs[r][px];
        }
    }
#pragma unroll
    for (int oo = 0; oo < 8; oo++) {
        float b = qb[o0+oo];
#pragma unroll
        for (int px = 0; px < 8; px++)
            so[(o0+oo)*132 + px0 + px] = acc[oo][px] + b;
    }
    __syncthreads();

    const float qs = rsqrtf(24.0f);
    // write q/k/v into per-head coset layout
    for (int f = tid; f < 3*128*12; f += 288) {
        int tensor = f / 1536;
        int rem = f % 1536;
        int px = rem / 12;
        int c12 = rem % 12;
        int n = c12 / 6, hc4 = c12 % 6;
        int o = tensor*48 + c12*4;
        float4 v;
        v.x = so[(o+0)*132 + px];
        v.y = so[(o+1)*132 + px];
        v.z = so[(o+2)*132 + px];
        v.w = so[(o+3)*132 + px];
        int p = p0 + px;
        int i = p / WW, j = p % WW;
        int cs = (i%3)*3 + (j%3);
        int cpix = (i/3)*CG + (j/3);
        size_t dsti = ((size_t)(n*9 + cs)*CG*CG + cpix)*HD + hc4*4;
        float* dst = (tensor == 0) ? g_qc : (tensor == 1) ? g_kc : g_vc;
        if (tensor == 0) { v.x*=qs; v.y*=qs; v.z*=qs; v.w*=qs; }
        *(float4*)&dst[dsti] = v;
    }
}

// ---------------- K2: coset-tiled neighborhood attention ----------------
// grid: (16 tiles, 9 cosets, 2 heads); block 256 = 16x16 coset pixels
// smem: sk[484][28] + sv[484][28] + srpb[169]
#define CHS 28
#define ATTN_SMEM ((484*CHS*2 + 176)*4)
__global__ void __launch_bounds__(256, 2) attn_kernel(const float* __restrict__ rpb) {
    extern __shared__ float sm[];
    float* sk = sm;                 // [484][28]
    float* sv = sm + 484*CHS;       // [484][28]
    float* srpb = sm + 2*484*CHS;   // [169]
    int tid = threadIdx.x;
    int tr = blockIdx.x >> 2, tc = blockIdx.x & 3;
    int cs = blockIdx.y;
    int n  = blockIdx.z;
    int r0 = tr * 16, c0 = tc * 16;
    int rbase = r0 - 3, cbase = c0 - 3;
    size_t tbase = (size_t)(n*9 + cs)*CG*CG;

    for (int i = tid; i < 169; i += 256) srpb[i] = rpb[n*169 + i];
    for (int idx = tid; idx < 2*2904; idx += 256) {
        int tsel = idx >= 2904;
        int e = tsel ? idx - 2904 : idx;
        int pos = e / 6, c4 = e % 6;
        int lr = pos / 22, lc = pos % 22;
        int grow = rbase + lr, gcol = cbase + lc;
        if (grow >= 0 && grow < CG && gcol >= 0 && gcol < CG) {
            const float* gsrc = tsel ? g_vc : g_kc;
            float* dst = tsel ? sv : sk;
            float4 val = *(const float4*)&gsrc[(tbase + grow*CG + gcol)*HD + c4*4];
            *(float4*)&dst[pos*CHS + c4*4] = val;
        }
    }
    __syncthreads();

    int tx = tid & 15, ty = tid >> 4;
    int ii = r0 + ty, jj = c0 + tx;
    int ssr = ii - 3; if (ssr < 0) ssr = 0; if (ssr > CG-KK) ssr = CG-KK;
    int ssc = jj - 3; if (ssc < 0) ssc = 0; if (ssc > CG-KK) ssc = CG-KK;
    int lr0 = ssr - rbase, lc0 = ssc - cbase;
    int pbh0 = ssr - ii + 6, pbw0 = ssc - jj + 6;

    float qreg[HD];
    {
        const float4* qp = (const float4*)&g_qc[(tbase + (size_t)ii*CG + jj)*HD];
#pragma unroll
        for (int c = 0; c < 6; c++) {
            float4 v4 = qp[c];
            qreg[4*c]=v4.x; qreg[4*c+1]=v4.y; qreg[4*c+2]=v4.z; qreg[4*c+3]=v4.w;
        }
    }

    float m = -1e30f, s = 0.f;
    float acc[HD];
#pragma unroll
    for (int c = 0; c < HD; c++) acc[c] = 0.f;

    for (int x = 0; x < KK; x++) {
        int rowb = (lr0 + x) * 22 + lc0;
        const float* brow = srpb + (pbh0 + x)*13 + pbw0;
#pragma unroll
        for (int y = 0; y < KK; y++) {
            const float* kb = sk + (rowb + y) * CHS;
            float d = 0.f;
#pragma unroll
            for (int c = 0; c < 6; c++) {
                float4 kk = *(const float4*)(kb + 4*c);
                d += qreg[4*c]*kk.x + qreg[4*c+1]*kk.y + qreg[4*c+2]*kk.z + qreg[4*c+3]*kk.w;
            }
            d += brow[y];
            if (d > m) {
                float f = __expf(m - d);
                s *= f;
#pragma unroll
                for (int c = 0; c < HD; c++) acc[c] *= f;
                m = d;
            }
            float w = __expf(d - m);
            s += w;
            const float* vb = sv + (rowb + y) * CHS;
#pragma unroll
            for (int c = 0; c < 6; c++) {
                float4 vv = *(const float4*)(vb + 4*c);
                acc[4*c]   += w*vv.x; acc[4*c+1] += w*vv.y;
                acc[4*c+2] += w*vv.z; acc[4*c+3] += w*vv.w;
            }
        }
    }
    float inv = 1.f / s;
    int a = cs / 3, b = cs % 3;
    int gp = (a + 3*ii)*WW + (b + 3*jj);
    float4* op = (float4*)&g_attn[(size_t)gp*CDIM + n*HD];
#pragma unroll
    for (int c = 0; c < 6; c++)
        op[c] = make_float4(acc[4*c]*inv, acc[4*c+1]*inv, acc[4*c+2]*inv, acc[4*c+3]*inv);
}

// ---------------- K3: proj + ECA gate + residual + LN2 fused ----------------
#define PROJ_SMEM ((48*48 + 48*132 + 48*132 + 48 + 48)*4)
__global__ void __launch_bounds__(192) proj_kernel(const float* __restrict__ x,
                            const float* __restrict__ pw,
                            const float* __restrict__ pb,
                            const float* __restrict__ ew,
                            const float* __restrict__ ln2w,
                            const float* __restrict__ ln2b,
                            float* __restrict__ out) {
    extern __shared__ float sm[];
    float* sw = sm;                 // [48][48]
    float* sa = sm + 48*48;         // [48][132]
    float* so = sa + 48*132;        // [48][132]
    float* smean = so + 48*132;     // [48]
    float* sgate = smean + 48;      // [48]
    int tid = threadIdx.x;
    int p0 = blockIdx.x * 128;

    for (int i = tid; i < 48*48; i += 192) sw[i] = pw[i];
    for (int i = tid; i < 48*128; i += 192) {
        int px = i / 48, c = i % 48;
        sa[c*132 + px] = g_attn[(size_t)(p0+px)*CDIM + c];
    }
    if (tid < 48) {
        float s = 0.f;
        for (int k = 0; k < NQKVBLK; k++) s += g_pmean_part[k*48 + tid];
        smean[tid] = s * (1.f/HWXY);
    }
    __syncthreads();
    if (tid < 48) {
        float s = 0.f;
#pragma unroll
        for (int k = 0; k < 7; k++) {
            int cc = tid - 3 + k;
            if (cc >= 0 && cc < CDIM) s += ew[k] * smean[cc];
        }
        sgate[tid] = 1.f / (1.f + expf(-s));
    }

    int og = tid >> 4, pg = tid & 15;
    int o0 = og * 4, px0 = pg * 8;
    float acc[4][8];
#pragma unroll
    for (int a = 0; a < 4; a++)
#pragma unroll
        for (int bi = 0; bi < 8; bi++) acc[a][bi] = 0.f;

    for (int c4 = 0; c4 < 48; c4 += 4) {
        float xs[4][8];
#pragma unroll
        for (int r = 0; r < 4; r++) {
            float4 a = *(const float4*)&sa[(c4+r)*132 + px0];
            float4 b = *(const float4*)&sa[(c4+r)*132 + px0 + 4];
            xs[r][0]=a.x; xs[r][1]=a.y; xs[r][2]=a.z; xs[r][3]=a.w;
            xs[r][4]=b.x; xs[r][5]=b.y; xs[r][6]=b.z; xs[r][7]=b.w;
        }
#pragma unroll
        for (int oo = 0; oo < 4; oo++) {
            float4 w4 = *(const float4*)&sw[(o0+oo)*48 + c4];
            float wv[4] = {w4.x, w4.y, w4.z, w4.w};
#pragma unroll
            for (int r = 0; r < 4; r++)
#pragma unroll
                for (int px = 0; px < 8; px++)
                    acc[oo][px] += wv[r] * xs[r][px];
        }
    }
    __syncthreads();

#pragma unroll
    for (int oo = 0; oo < 4; oo++) {
        int o = o0 + oo;
        float g = sgate[o];
        float b = pb[o];
        float4 xv1 = *(const float4*)&x[(size_t)o*HWXY + p0 + px0];
        float4 xv2 = *(const float4*)&x[(size_t)o*HWXY + p0 + px0 + 4];
        float vals[8];
        vals[0] = xv1.x + g*(acc[oo][0]+b); vals[1] = xv1.y + g*(acc[oo][1]+b);
        vals[2] = xv1.z + g*(acc[oo][2]+b); vals[3] = xv1.w + g*(acc[oo][3]+b);
        vals[4] = xv2.x + g*(acc[oo][4]+b); vals[5] = xv2.y + g*(acc[oo][5]+b);
        vals[6] = xv2.z + g*(acc[oo][6]+b); vals[7] = xv2.w + g*(acc[oo][7]+b);
        *(float4*)&out[(size_t)o*HWXY + p0 + px0]     = make_float4(vals[0],vals[1],vals[2],vals[3]);
        *(float4*)&out[(size_t)o*HWXY + p0 + px0 + 4] = make_float4(vals[4],vals[5],vals[6],vals[7]);
#pragma unroll
        for (int px = 0; px < 8; px++) so[o*132 + px0 + px] = vals[px];
    }
    __syncthreads();

    if (tid < 128) {
        int px = tid;
        float v[CDIM];
        float s = 0.f;
#pragma unroll
        for (int c = 0; c < CDIM; c++) { v[c] = so[c*132 + px]; s += v[c]; }
        float mu = s * (1.f/CDIM);
        float var = 0.f;
#pragma unroll
        for (int c = 0; c < CDIM; c++) { float d = v[c]-mu; var += d*d; }
        float inv = rsqrtf(var*(1.f/CDIM) + 1e-5f);
#pragma unroll
        for (int c = 0; c < CDIM; c++)
            g_xn2[c*HWXY + p0 + px] = (v[c]-mu)*inv*ln2w[c] + ln2b[c];
    }
}

// ---------------- K4: FFN in-projection ----------------
#define FIN_SMEM ((256*48 + 48*128)*4)
__global__ void __launch_bounds__(512) ffn_in_kernel(const float* __restrict__ wi) {
    extern __shared__ float sm[];
    float* sw = sm;               // [256][48], rows >=254 zero
    float* sx = sm + 256*48;      // [48][128]
    int tid = threadIdx.x;
    int p0 = blockIdx.x * 128;

    for (int i = tid; i < 256*48; i += 512) sw[i] = (i < HID2*48) ? wi[i] : 0.f;
    for (int i = tid; i < 48*128; i += 512) {
        int c = i >> 7, px = i & 127;
        sx[i] = g_xn2[c*HWXY + p0 + px];
    }
    __syncthreads();

    int og = tid >> 4, pg = tid & 15;
    int o0 = og * 8, px0 = pg * 8;
    float acc[8][8];
#pragma unroll
    for (int a = 0; a < 8; a++)
#pragma unroll
        for (int bi = 0; bi < 8; bi++) acc[a][bi] = 0.f;

    for (int c4 = 0; c4 < 48; c4 += 4) {
        float xs[4][8];
#pragma unroll
        for (int r = 0; r < 4; r++) {
            float4 a = *(const float4*)&sx[(c4+r)*128 + px0];
            float4 b = *(const float4*)&sx[(c4+r)*128 + px0 + 4];
            xs[r][0]=a.x; xs[r][1]=a.y; xs[r][2]=a.z; xs[r][3]=a.w;
            xs[r][4]=b.x; xs[r][5]=b.y; xs[r][6]=b.z; xs[r][7]=b.w;
        }
#pragma unroll
        for (int oo = 0; oo < 8; oo++) {
            float4 w4 = *(const float4*)&sw[(o0+oo)*48 + c4];
            float wv[4] = {w4.x, w4.y, w4.z, w4.w};
#pragma unroll
            for (int r = 0; r < 4; r++)
#pragma unroll
                for (int px = 0; px < 8; px++)
                    acc[oo][px] += wv[r] * xs[r][px];
        }
    }
#pragma unroll
    for (int oo = 0; oo < 8; oo++) {
        int o = o0 + oo;
        if (o < HID2) {
            *(float4*)&g_t[(size_t)o*HWXY + p0 + px0]     = make_float4(acc[oo][0],acc[oo][1],acc[oo][2],acc[oo][3]);
            *(float4*)&g_t[(size_t)o*HWXY + p0 + px0 + 4] = make_float4(acc[oo][4],acc[oo][5],acc[oo][6],acc[oo][7]);
        }
    }
}

// ---------------- K5: depthwise 3x3 + exact-gelu gating ----------------
__global__ void dwgelu_kernel(const float* __restrict__ wdw) {
    __shared__ float sA[6*192];
    __shared__ float sB[6*192];
    __shared__ float swc[18];
    int o = blockIdx.y;
    int r0 = blockIdx.x * 4;
    int tid = threadIdx.x;

    if (tid < 9)  swc[tid] = wdw[o*9 + tid];
    else if (tid < 18) swc[tid] = wdw[(o+HID)*9 + tid - 9];

    for (int i = tid; i < 6*192; i += 256) {
        int rr = i / 192, col = i - rr*192;
        int row = r0 - 1 + rr;
        bool ok = (row >= 0) && (row < HH);
        sA[i] = ok ? g_t[(size_t)o*HWXY + row*WW + col] : 0.f;
        sB[i] = ok ? g_t[(size_t)(o+HID)*HWXY + row*WW + col] : 0.f;
    }
    __syncthreads();

    for (int idx = tid; idx < 4*192; idx += 256) {
        int orow = idx / 192, col = idx - orow*192;
        int sbase = (orow + 1) * 192 + col;
        float a = 0.f, bb = 0.f;
#pragma unroll
        for (int ky = 0; ky < 3; ky++) {
            int rb = sbase + (ky-1)*192;
#pragma unroll
            for (int kx = 0; kx < 3; kx++) {
                int cc = col + kx - 1;
                if (cc < 0 || cc >= WW) continue;
                a  += swc[ky*3+kx]     * sA[rb + kx - 1];
                bb += swc[9 + ky*3+kx] * sB[rb + kx - 1];
            }
        }
        float ge = 0.5f * a * (1.f + erff(a * 0.70710678118654752f));
        g_g[(size_t)o*HWXY + (r0+orow)*WW + col] = ge * bb;
    }
}

// ---------------- K6: FFN out-projection + residual ----------------
#define FOUT_SMEM ((48*128 + 128*128)*4)
__global__ void __launch_bounds__(192) ffn_out_kernel(const float* __restrict__ wo,
                               float* __restrict__ out) {
    extern __shared__ float sm[];
    float* sw = sm;             // [48][128]
    float* sg = sm + 48*128;    // [128][128]
    int tid = threadIdx.x;
    int p0 = blockIdx.x * 128;

    for (int i = tid; i < 48*128; i += 192) {
        int o = i >> 7, c = i & 127;
        sw[i] = (c < HID) ? wo[o*HID + c] : 0.f;
    }
    for (int i = tid; i < 128*128; i += 192) {
        int c = i >> 7, px = i & 127;
        sg[i] = (c < HID) ? g_g[(size_t)c*HWXY + p0 + px] : 0.f;
    }
    __syncthreads();

    int og = tid >> 4, pg = tid & 15;
    int o0 = og * 4, px0 = pg * 8;
    float acc[4][8];
#pragma unroll
    for (int a = 0; a < 4; a++)
#pragma unroll
        for (int bi = 0; bi < 8; bi++) acc[a][bi] = 0.f;

    for (int c4 = 0; c4 < 128; c4 += 4) {
        float xs[4][8];
#pragma unroll
        for (int r = 0; r < 4; r++) {
            float4 a = *(const float4*)&sg[(c4+r)*128 + px0];
            float4 b = *(const float4*)&sg[(c4+r)*128 + px0 + 4];
            xs[r][0]=a.x; xs[r][1]=a.y; xs[r][2]=a.z; xs[r][3]=a.w;
            xs[r][4]=b.x; xs[r][5]=b.y; xs[r][6]=b.z; xs[r][7]=b.w;
        }
#pragma unroll
        for (int oo = 0; oo < 4; oo++) {
            float4 w4 = *(const float4*)&sw[(o0+oo)*128 + c4];
            float wv[4] = {w4.x, w4.y, w4.z, w4.w};
#pragma unroll
            for (int r = 0; r < 4; r++)
#pragma unroll
                for (int px = 0; px < 8; px++)
                    acc[oo][px] += wv[r] * xs[r][px];
        }
    }
#pragma unroll
    for (int oo = 0; oo < 4; oo++) {
        int o = o0 + oo;
        float4* op1 = (float4*)&out[(size_t)o*HWXY + p0 + px0];
        float4* op2 = (float4*)&out[(size_t)o*HWXY + p0 + px0 + 4];
        float4 c1 = *op1, c2 = *op2;
        c1.x += acc[oo][0]; c1.y += acc[oo][1]; c1.z += acc[oo][2]; c1.w += acc[oo][3];
        c2.x += acc[oo][4]; c2.y += acc[oo][5]; c2.z += acc[oo][6]; c2.w += acc[oo][7];
        *op1 = c1; *op2 = c2;
    }
}

// ---------------- launch ----------------
extern "C" void kernel_launch(void* const* d_in, const int* in_sizes, int n_in,
                              void* d_out, int out_size) {
    const float* x      = (const float*)d_in[0];
    const float* ln1_w  = (const float*)d_in[1];
    const float* ln1_b  = (const float*)d_in[2];
    const float* qkv_w  = (const float*)d_in[3];
    const float* qkv_b  = (const float*)d_in[4];
    const float* rpb    = (const float*)d_in[5];
    const float* proj_w = (const float*)d_in[6];
    const float* proj_b = (const float*)d_in[7];
    const float* eca_w  = (const float*)d_in[8];
    const float* ln2_w  = (const float*)d_in[9];
    const float* ln2_b  = (const float*)d_in[10];
    const float* w_in   = (const float*)d_in[11];
    const float* w_dw   = (const float*)d_in[12];
    const float* w_out  = (const float*)d_in[13];
    float* out = (float*)d_out;

    cudaFuncSetAttribute(qkv_kernel,     cudaFuncAttributeMaxDynamicSharedMemorySize, QKV_SMEM);
    cudaFuncSetAttribute(attn_kernel,    cudaFuncAttributeMaxDynamicSharedMemorySize, ATTN_SMEM);
    cudaFuncSetAttribute(proj_kernel,    cudaFuncAttributeMaxDynamicSharedMemorySize, PROJ_SMEM);
    cudaFuncSetAttribute(ffn_in_kernel,  cudaFuncAttributeMaxDynamicSharedMemorySize, FIN_SMEM);
    cudaFuncSetAttribute(ffn_out_kernel, cudaFuncAttributeMaxDynamicSharedMemorySize, FOUT_SMEM);

    qkv_kernel<<<NQKVBLK, 288, QKV_SMEM>>>(x, ln1_w, ln1_b, qkv_w, qkv_b);
    attn_kernel<<<dim3(16, 9, 2), 256, ATTN_SMEM>>>(rpb);
    proj_kernel<<<HWXY/128, 192, PROJ_SMEM>>>(x, proj_w, proj_b, eca_w, ln2_w, ln2_b, out);
    ffn_in_kernel<<<HWXY/128, 512, FIN_SMEM>>>(w_in);
    dwgelu_kernel<<<dim3(HH/4, HID), 256>>>(w_dw);
    ffn_out_kernel<<<HWXY/128, 192, FOUT_SMEM>>>(w_out, out);
}